// round 13
// baseline (speedup 1.0000x reference)
#include <cuda_runtime.h>
#include <cuda_fp16.h>
#include <cstdint>
#include <math.h>

// Problem constants (B=4, S=2048 -> T=8192 tokens)
#define T_TOK 8192
#define H_DIM 1024
#define F_DIM 4096
#define NEXP  8

// GEMM tile: 128x128x64, fp16 mma.sync m16n8k16, 8 warps (4x2),
// 4-stage cp.async, ONE __syncthreads per K-iteration,
// double-buffered ldmatrix fragments.
#define BM 128
#define BN 128
#define BK 64
#define NSTAGE 4
#define A_STRIDE 144                  // bytes per A smem row (128 data + 16 pad)
#define B_STRIDE 272                  // bytes per B smem row (256 data + 16 pad)
#define A_BYTES (BM * A_STRIDE)       // 18432
#define B_BYTES (BK * B_STRIDE)       // 17408
#define STAGE_BYTES (A_BYTES + B_BYTES)   // 35840
#define SM_TOTAL (NSTAGE * STAGE_BYTES)   // 143360

// ---- persistent scratch (device globals: allocation-free kernel_launch) ----
__device__ int    g_count[NEXP];
__device__ int    g_offset[NEXP];
__device__ int    g_perm[NEXP * T_TOK];
__device__ float  g_wslot[T_TOK * 2];
__device__ __half g_xh[(size_t)T_TOK * H_DIM];
__device__ __half g_w1h[(size_t)NEXP * H_DIM * F_DIM];
__device__ __half g_w2h[(size_t)NEXP * F_DIM * H_DIM];
__device__ __half g_hbuf[(size_t)T_TOK * 2 * F_DIM];   // gelu(x@w1+b1), compact fp16 rows
__device__ float  g_ybuf[(size_t)T_TOK * 2 * H_DIM];   // per-slot expert output (fp32)

// ---------------------------------------------------------------------------
__device__ __forceinline__ uint32_t smem_u32(const void* p) {
    uint32_t a;
    asm("{ .reg .u64 t; cvta.to.shared.u64 t, %1; cvt.u32.u64 %0, t; }" : "=r"(a) : "l"(p));
    return a;
}

#define CP_ASYNC16(dst, src, sz) \
    asm volatile("cp.async.cg.shared.global [%0], [%1], 16, %2;" \
                 :: "r"(dst), "l"(src), "r"(sz) : "memory")
#define CP_COMMIT()  asm volatile("cp.async.commit_group;" ::: "memory")
#define CP_WAITG(n)  asm volatile("cp.async.wait_group %0;" :: "n"(n) : "memory")

#define LDSM_X4(r0, r1, r2, r3, a) \
    asm volatile("ldmatrix.sync.aligned.m8n8.x4.shared.b16 {%0,%1,%2,%3}, [%4];" \
                 : "=r"(r0), "=r"(r1), "=r"(r2), "=r"(r3) : "r"(a))
#define LDSM_X4_T(r0, r1, r2, r3, a) \
    asm volatile("ldmatrix.sync.aligned.m8n8.x4.trans.shared.b16 {%0,%1,%2,%3}, [%4];" \
                 : "=r"(r0), "=r"(r1), "=r"(r2), "=r"(r3) : "r"(a))

#define MMA16816(c0, c1, c2, c3, a0, a1, a2, a3, b0, b1) \
    asm volatile("mma.sync.aligned.m16n8k16.row.col.f32.f16.f16.f32 " \
                 "{%0,%1,%2,%3}, {%4,%5,%6,%7}, {%8,%9}, {%0,%1,%2,%3};" \
                 : "+f"(c0), "+f"(c1), "+f"(c2), "+f"(c3) \
                 : "r"(a0), "r"(a1), "r"(a2), "r"(a3), "r"(b0), "r"(b1))

// ---------------------------------------------------------------------------
__global__ void scan_kernel() {
    int s = 0;
    for (int e = 0; e < NEXP; e++) { g_offset[e] = s; s += g_count[e]; }
}

// Router (one warp/token) + fused x -> fp16 conversion (x is streamed anyway).
__global__ __launch_bounds__(256)
void router_kernel(const float* __restrict__ x,
                   const float* __restrict__ rw,
                   const float* __restrict__ rb) {
    int warp = (blockIdx.x * blockDim.x + threadIdx.x) >> 5;
    int lane = threadIdx.x & 31;
    if (warp >= T_TOK) return;
    const float* xr = x + (size_t)warp * H_DIM;
    __half* xo = g_xh + (size_t)warp * H_DIM;
    float acc[NEXP];
#pragma unroll
    for (int e = 0; e < NEXP; e++) acc[e] = 0.f;
    for (int h = lane; h < H_DIM; h += 32) {
        float xv = xr[h];
        xo[h] = __float2half_rn(xv);
        const float* w = rw + h * NEXP;
#pragma unroll
        for (int e = 0; e < NEXP; e++) acc[e] += xv * w[e];
    }
#pragma unroll
    for (int e = 0; e < NEXP; e++)
#pragma unroll
        for (int s = 16; s > 0; s >>= 1)
            acc[e] += __shfl_xor_sync(0xffffffffu, acc[e], s);
    if (lane == 0) {
#pragma unroll
        for (int e = 0; e < NEXP; e++) acc[e] += rb[e];
        int e0 = 0;
#pragma unroll
        for (int e = 1; e < NEXP; e++) if (acc[e] > acc[e0]) e0 = e;
        int e1 = (e0 == 0) ? 1 : 0;
#pragma unroll
        for (int e = 0; e < NEXP; e++)
            if (e != e0 && acc[e] > acc[e1]) e1 = e;
        float r  = expf(acc[e1] - acc[e0]);
        float w0 = 1.f / (1.f + r);
        float w1 = r / (1.f + r);
        int s0 = warp * 2, s1 = warp * 2 + 1;
        int p0 = atomicAdd(&g_count[e0], 1);
        g_perm[e0 * T_TOK + p0] = s0;
        g_wslot[s0] = w0;
        int p1 = atomicAdd(&g_count[e1], 1);
        g_perm[e1 * T_TOK + p1] = s1;
        g_wslot[s1] = w1;
    }
}

// Streaming fp32 -> fp16 convert, grid-stride, 32B read / 16B write per step.
// zflag: block 0 additionally zeroes the per-expert counters.
__global__ __launch_bounds__(256)
void f32_to_f16_kernel(const float* __restrict__ s, __half* __restrict__ d,
                       int n8, int zflag) {
    if (zflag && blockIdx.x == 0 && threadIdx.x < NEXP) g_count[threadIdx.x] = 0;
    int stride = gridDim.x * blockDim.x;
    for (int i = blockIdx.x * blockDim.x + threadIdx.x; i < n8; i += stride) {
        float4 v0 = __ldcs((const float4*)s + 2 * i);
        float4 v1 = __ldcs((const float4*)s + 2 * i + 1);
        __half2 h0 = __floats2half2_rn(v0.x, v0.y);
        __half2 h1 = __floats2half2_rn(v0.z, v0.w);
        __half2 h2 = __floats2half2_rn(v1.x, v1.y);
        __half2 h3 = __floats2half2_rn(v1.z, v1.w);
        uint4 o;
        o.x = *reinterpret_cast<uint32_t*>(&h0);
        o.y = *reinterpret_cast<uint32_t*>(&h1);
        o.z = *reinterpret_cast<uint32_t*>(&h2);
        o.w = *reinterpret_cast<uint32_t*>(&h3);
        __stcs((uint4*)d + i, o);
    }
}

__device__ __forceinline__ float gelu_tanh(float v) {
    float v3 = v * v * v;
    float t  = tanhf(0.7978845608028654f * (v + 0.044715f * v3));
    return 0.5f * v * (1.f + t);
}

// ---------------------------------------------------------------------------
// Gathered per-expert fp16 GEMM. mma.sync m16n8k16, ldmatrix, 4-stage cp.async,
// one barrier per K-iteration, double-buffered fragments.
// MODE 0: hbuf = fp16(gelu(Xgather @ w1 + b1)),  A = g_xh gathered, KD = H
// MODE 1: ybuf = hbuf @ w2 + b2 (scatter rows),  A = g_hbuf compact, KD = F
// ---------------------------------------------------------------------------
template<int KD, int MODE>
__global__ __launch_bounds__(256)
void moe_gemm(const __half* __restrict__ Ah,
              const __half* __restrict__ W,
              const float* __restrict__ bias,
              int ND) {
    extern __shared__ __align__(128) char smem[];
    const uint32_t sb = smem_u32(smem);

    const int e    = blockIdx.z;
    const int cnt  = g_count[e];
    const int row0 = blockIdx.y * BM;
    if (row0 >= cnt) return;
    const int col0 = blockIdx.x * BN;
    const int off  = g_offset[e];

    const int tid  = threadIdx.x;
    const int lane = tid & 31, wid = tid >> 5;
    const int wm = wid & 3, wn = wid >> 2;       // 4x2 warp grid, warp tile 32x64

    // ---- cp.async staging (register-lean: bases + u32 offsets + bitmask) ----
    // A: 128 rows x 128B data. 8 segs/row; thread covers 4 rows (ar0 + 32i).
    const int segA = tid & 7;
    const int ar0  = tid >> 3;
    const char* Abase = (const char*)Ah + segA * 16;
    uint32_t aGOff[4]; uint32_t avMask = 0;
#pragma unroll
    for (int i = 0; i < 4; i++) {
        int r = ar0 + 32 * i;
        bool v = (row0 + r) < cnt;
        uint32_t srow;
        if (MODE == 0) srow = v ? (uint32_t)(g_perm[e * T_TOK + row0 + r] >> 1) : 0u;
        else           srow = (uint32_t)(off + (v ? row0 + r : 0));
        aGOff[i] = srow * (uint32_t)(KD * 2);
        if (v) avMask |= (1u << i);
    }
    const uint32_t aDst0 = (uint32_t)(ar0 * A_STRIDE + segA * 16);
    // B: 64 rows x 256B data. 16 segs/row; thread covers 4 rows (br0 + 16i).
    const int segB = tid & 15;
    const int br0  = tid >> 4;
    const char* Bbase = (const char*)(W + (size_t)e * KD * ND + col0 + segB * 8)
                      + (size_t)br0 * ND * 2;
    const uint32_t bStep16 = (uint32_t)(16 * ND * 2);
    const uint32_t kbStep  = (uint32_t)(BK * ND * 2);
    const uint32_t bDst0   = (uint32_t)(br0 * B_STRIDE + segB * 16);

    auto issue_tile = [&](uint32_t ktA, uint32_t kbOff, int st) {
        uint32_t aB = sb + st * STAGE_BYTES;
        uint32_t bB = aB + A_BYTES;
        uint32_t ad = aB + aDst0;
#pragma unroll
        for (int i = 0; i < 4; i++) {
            CP_ASYNC16(ad, Abase + aGOff[i] + ktA, ((avMask >> i) & 1) ? 16u : 0u);
            ad += 32 * A_STRIDE;
        }
        uint32_t bd = bB + bDst0;
        const char* bs = Bbase + kbOff;
#pragma unroll
        for (int i = 0; i < 4; i++) {
            CP_ASYNC16(bd, bs, 16u);
            bd += 16 * B_STRIDE;
            bs += bStep16;
        }
    };

    // ---- ldmatrix fragment offsets (stage-relative) ----
    int aOff[2];
#pragma unroll
    for (int mf = 0; mf < 2; mf++)
        aOff[mf] = (wm * 32 + mf * 16 + (lane & 15)) * A_STRIDE + (lane >> 4) * 16;
    const int bRow = (lane & 7) + ((lane >> 3) & 1) * 8;
    int bOff[4];
#pragma unroll
    for (int p = 0; p < 4; p++)
        bOff[p] = bRow * B_STRIDE + (wn * 64 + p * 16 + (lane >> 4) * 8) * 2;

    float c[2][8][4];
#pragma unroll
    for (int i = 0; i < 2; i++)
#pragma unroll
        for (int j = 0; j < 8; j++)
#pragma unroll
            for (int q = 0; q < 4; q++) c[i][j][q] = 0.f;

    // double-buffered fragments
    uint32_t af[2][2][4], bf[2][8][2];
    auto load_frags = [&](uint32_t aB, uint32_t bB, int ks, int b) {
#pragma unroll
        for (int mf = 0; mf < 2; mf++)
            LDSM_X4(af[b][mf][0], af[b][mf][1], af[b][mf][2], af[b][mf][3],
                    aB + aOff[mf] + ks * 32);
#pragma unroll
        for (int p = 0; p < 4; p++)
            LDSM_X4_T(bf[b][2 * p][0], bf[b][2 * p][1],
                      bf[b][2 * p + 1][0], bf[b][2 * p + 1][1],
                      bB + bOff[p] + ks * 16 * B_STRIDE);
    };

    const int nk = KD / BK;
    uint32_t nxtA = 0, nxtB = 0;
#pragma unroll
    for (int s = 0; s < NSTAGE - 1; s++) {
        issue_tile(nxtA, nxtB, s);
        CP_COMMIT();
        nxtA += BK * 2; nxtB += kbStep;
    }

    for (int kt = 0; kt < nk; kt++) {
        CP_WAITG(NSTAGE - 2);      // groups committed every iter -> tile kt landed
        __syncthreads();           // stage (kt-1)%NSTAGE now reusable
        int nt = kt + NSTAGE - 1;
        if (nt < nk) {
            issue_tile(nxtA, nxtB, nt % NSTAGE);
            nxtA += BK * 2; nxtB += kbStep;
        }
        CP_COMMIT();               // unconditional: keeps group accounting uniform

        uint32_t aB = sb + (kt % NSTAGE) * STAGE_BYTES;
        uint32_t bB = aB + A_BYTES;
        load_frags(aB, bB, 0, 0);
#pragma unroll
        for (int ks = 0; ks < 4; ks++) {       // 4 x K=16 = BK
            const int cur = ks & 1;
            if (ks < 3) load_frags(aB, bB, ks + 1, cur ^ 1);
#pragma unroll
            for (int mf = 0; mf < 2; mf++)
#pragma unroll
                for (int nf = 0; nf < 8; nf++)
                    MMA16816(c[mf][nf][0], c[mf][nf][1], c[mf][nf][2], c[mf][nf][3],
                             af[cur][mf][0], af[cur][mf][1], af[cur][mf][2], af[cur][mf][3],
                             bf[cur][nf][0], bf[cur][nf][1]);
        }
    }
    CP_WAITG(0);

    // ---- epilogue: c frag rows (g, g+8), cols (2*tg, 2*tg+1) ----
    const int g  = lane >> 2, tg = lane & 3;
    const float* bz = bias + e * ND + col0;
#pragma unroll
    for (int mf = 0; mf < 2; mf++) {
#pragma unroll
        for (int hh = 0; hh < 2; hh++) {
            int r    = wm * 32 + mf * 16 + g + hh * 8;
            int grow = row0 + r;
            if (grow >= cnt) continue;
            size_t drow;
            if (MODE == 0) drow = (size_t)(off + grow) * F_DIM;
            else           drow = (size_t)g_perm[e * T_TOK + grow] * H_DIM;
#pragma unroll
            for (int nf = 0; nf < 8; nf++) {
                int cn   = wn * 64 + nf * 8 + 2 * tg;
                float v0 = c[mf][nf][hh * 2 + 0] + bz[cn];
                float v1 = c[mf][nf][hh * 2 + 1] + bz[cn + 1];
                if (MODE == 0) {
                    *(__half2*)&g_hbuf[drow + col0 + cn] =
                        __floats2half2_rn(gelu_tanh(v0), gelu_tanh(v1));
                } else {
                    *(float2*)&g_ybuf[drow + col0 + cn] = make_float2(v0, v1);
                }
            }
        }
    }
}

// ---------------------------------------------------------------------------
__global__ __launch_bounds__(256)
void combine_kernel(float* __restrict__ out) {
    int idx = blockIdx.x * blockDim.x + threadIdx.x;   // over T*H/4
    if (idx >= T_TOK * H_DIM / 4) return;
    int t  = idx >> 8;           // H_DIM/4 = 256
    int h4 = (idx & 255) * 4;
    float w0 = g_wslot[2 * t], w1 = g_wslot[2 * t + 1];
    float4 a = *(const float4*)&g_ybuf[(size_t)(2 * t)     * H_DIM + h4];
    float4 b = *(const float4*)&g_ybuf[(size_t)(2 * t + 1) * H_DIM + h4];
    float4 o;
    o.x = w0 * a.x + w1 * b.x;
    o.y = w0 * a.y + w1 * b.y;
    o.z = w0 * a.z + w1 * b.z;
    o.w = w0 * a.w + w1 * b.w;
    ((float4*)out)[idx] = o;
}

// ---------------------------------------------------------------------------
extern "C" void kernel_launch(void* const* d_in, const int* in_sizes, int n_in,
                              void* d_out, int out_size) {
    const float* x  = (const float*)d_in[0];
    const float* w1 = (const float*)d_in[1];
    const float* b1 = (const float*)d_in[2];
    const float* w2 = (const float*)d_in[3];
    const float* b2 = (const float*)d_in[4];
    const float* rw = (const float*)d_in[5];
    const float* rb = (const float*)d_in[6];
    float* out = (float*)d_out;

    cudaFuncSetAttribute(moe_gemm<H_DIM, 0>, cudaFuncAttributeMaxDynamicSharedMemorySize, SM_TOTAL);
    cudaFuncSetAttribute(moe_gemm<F_DIM, 1>, cudaFuncAttributeMaxDynamicSharedMemorySize, SM_TOTAL);

    __half *w1h, *w2h, *xh, *hb;
    cudaGetSymbolAddress((void**)&w1h, g_w1h);
    cudaGetSymbolAddress((void**)&w2h, g_w2h);
    cudaGetSymbolAddress((void**)&xh,  g_xh);
    cudaGetSymbolAddress((void**)&hb,  g_hbuf);

    // weight converts first; the first one also zeroes the expert counters
    {
        int n8 = NEXP * H_DIM * F_DIM / 8;
        f32_to_f16_kernel<<<2048, 256>>>(w1, w1h, n8, 1);
        f32_to_f16_kernel<<<2048, 256>>>(w2, w2h, n8, 0);
    }
    router_kernel<<<T_TOK / 8, 256>>>(x, rw, rb);   // also emits g_xh (fp16)
    scan_kernel<<<1, 1>>>();

    dim3 g1(F_DIM / BN, T_TOK / BM, NEXP);   // 32 x 64 x 8
    moe_gemm<H_DIM, 0><<<g1, 256, SM_TOTAL>>>(xh, w1h, b1, F_DIM);

    dim3 g2(H_DIM / BN, T_TOK / BM, NEXP);   // 8 x 64 x 8
    moe_gemm<F_DIM, 1><<<g2, 256, SM_TOTAL>>>(hb, w2h, b2, H_DIM);

    combine_kernel<<<(T_TOK * H_DIM / 4 + 255) / 256, 256>>>(out);
}

// round 15
// speedup vs baseline: 1.3030x; 1.3030x over previous
#include <cuda_runtime.h>
#include <cuda_fp16.h>
#include <cstdint>
#include <math.h>

// Problem constants (B=4, S=2048 -> T=8192 tokens)
#define T_TOK 8192
#define H_DIM 1024
#define F_DIM 4096
#define NEXP  8

// GEMM tile: 128x128x64, fp16 mma.sync m16n8k16, 8 warps (4x2),
// 3-stage cp.async, ONE __syncthreads per K-iteration, 2 CTAs/SM.
#define BM 128
#define BN 128
#define BK 64
#define NSTAGE 3
#define A_STRIDE 144                  // bytes per A smem row (128 data + 16 pad)
#define B_STRIDE 272                  // bytes per B smem row (256 data + 16 pad)
#define A_BYTES (BM * A_STRIDE)       // 18432
#define B_BYTES (BK * B_STRIDE)       // 17408
#define STAGE_BYTES (A_BYTES + B_BYTES)   // 35840
#define SM_TOTAL (NSTAGE * STAGE_BYTES)   // 107520

// ---- persistent scratch (device globals: allocation-free kernel_launch) ----
__device__ int    g_count[NEXP];
__device__ int    g_offset[NEXP];
__device__ int    g_perm[NEXP * T_TOK];
__device__ float  g_wslot[T_TOK * 2];
__device__ __half g_xh[(size_t)T_TOK * H_DIM];
__device__ __half g_w1h[(size_t)NEXP * H_DIM * F_DIM];
__device__ __half g_w2h[(size_t)NEXP * F_DIM * H_DIM];
__device__ __half g_hbuf[(size_t)T_TOK * 2 * F_DIM];   // gelu(x@w1+b1), compact fp16 rows
__device__ float  g_ybuf[(size_t)T_TOK * 2 * H_DIM];   // per-slot expert output (fp32)

// ---------------------------------------------------------------------------
__device__ __forceinline__ uint32_t smem_u32(const void* p) {
    uint32_t a;
    asm("{ .reg .u64 t; cvta.to.shared.u64 t, %1; cvt.u32.u64 %0, t; }" : "=r"(a) : "l"(p));
    return a;
}

#define CP_ASYNC16(dst, src, sz) \
    asm volatile("cp.async.cg.shared.global [%0], [%1], 16, %2;" \
                 :: "r"(dst), "l"(src), "r"(sz) : "memory")
#define CP_COMMIT()  asm volatile("cp.async.commit_group;" ::: "memory")
#define CP_WAITG(n)  asm volatile("cp.async.wait_group %0;" :: "n"(n) : "memory")

#define LDSM_X4(r0, r1, r2, r3, a) \
    asm volatile("ldmatrix.sync.aligned.m8n8.x4.shared.b16 {%0,%1,%2,%3}, [%4];" \
                 : "=r"(r0), "=r"(r1), "=r"(r2), "=r"(r3) : "r"(a))
#define LDSM_X4_T(r0, r1, r2, r3, a) \
    asm volatile("ldmatrix.sync.aligned.m8n8.x4.trans.shared.b16 {%0,%1,%2,%3}, [%4];" \
                 : "=r"(r0), "=r"(r1), "=r"(r2), "=r"(r3) : "r"(a))

#define MMA16816(c0, c1, c2, c3, a0, a1, a2, a3, b0, b1) \
    asm volatile("mma.sync.aligned.m16n8k16.row.col.f32.f16.f16.f32 " \
                 "{%0,%1,%2,%3}, {%4,%5,%6,%7}, {%8,%9}, {%0,%1,%2,%3};" \
                 : "+f"(c0), "+f"(c1), "+f"(c2), "+f"(c3) \
                 : "r"(a0), "r"(a1), "r"(a2), "r"(a3), "r"(b0), "r"(b1))

// ---------------------------------------------------------------------------
__global__ void scan_kernel() {
    int s = 0;
    for (int e = 0; e < NEXP; e++) { g_offset[e] = s; s += g_count[e]; }
}

// Router (one warp/token) + fused x -> fp16 conversion (x is streamed anyway).
__global__ __launch_bounds__(256)
void router_kernel(const float* __restrict__ x,
                   const float* __restrict__ rw,
                   const float* __restrict__ rb) {
    int warp = (blockIdx.x * blockDim.x + threadIdx.x) >> 5;
    int lane = threadIdx.x & 31;
    if (warp >= T_TOK) return;
    const float* xr = x + (size_t)warp * H_DIM;
    __half* xo = g_xh + (size_t)warp * H_DIM;
    float acc[NEXP];
#pragma unroll
    for (int e = 0; e < NEXP; e++) acc[e] = 0.f;
    for (int h = lane; h < H_DIM; h += 32) {
        float xv = xr[h];
        xo[h] = __float2half_rn(xv);
        const float* w = rw + h * NEXP;
#pragma unroll
        for (int e = 0; e < NEXP; e++) acc[e] += xv * w[e];
    }
#pragma unroll
    for (int e = 0; e < NEXP; e++)
#pragma unroll
        for (int s = 16; s > 0; s >>= 1)
            acc[e] += __shfl_xor_sync(0xffffffffu, acc[e], s);
    if (lane == 0) {
#pragma unroll
        for (int e = 0; e < NEXP; e++) acc[e] += rb[e];
        int e0 = 0;
#pragma unroll
        for (int e = 1; e < NEXP; e++) if (acc[e] > acc[e0]) e0 = e;
        int e1 = (e0 == 0) ? 1 : 0;
#pragma unroll
        for (int e = 0; e < NEXP; e++)
            if (e != e0 && acc[e] > acc[e1]) e1 = e;
        float r  = expf(acc[e1] - acc[e0]);
        float w0 = 1.f / (1.f + r);
        float w1 = r / (1.f + r);
        int s0 = warp * 2, s1 = warp * 2 + 1;
        int p0 = atomicAdd(&g_count[e0], 1);
        g_perm[e0 * T_TOK + p0] = s0;
        g_wslot[s0] = w0;
        int p1 = atomicAdd(&g_count[e1], 1);
        g_perm[e1 * T_TOK + p1] = s1;
        g_wslot[s1] = w1;
    }
}

// Streaming fp32 -> fp16 convert, grid-stride, 32B read / 16B write per step.
// zflag: block 0 additionally zeroes the per-expert counters.
__global__ __launch_bounds__(256)
void f32_to_f16_kernel(const float* __restrict__ s, __half* __restrict__ d,
                       int n8, int zflag) {
    if (zflag && blockIdx.x == 0 && threadIdx.x < NEXP) g_count[threadIdx.x] = 0;
    int stride = gridDim.x * blockDim.x;
    for (int i = blockIdx.x * blockDim.x + threadIdx.x; i < n8; i += stride) {
        float4 v0 = __ldcs((const float4*)s + 2 * i);
        float4 v1 = __ldcs((const float4*)s + 2 * i + 1);
        __half2 h0 = __floats2half2_rn(v0.x, v0.y);
        __half2 h1 = __floats2half2_rn(v0.z, v0.w);
        __half2 h2 = __floats2half2_rn(v1.x, v1.y);
        __half2 h3 = __floats2half2_rn(v1.z, v1.w);
        uint4 o;
        o.x = *reinterpret_cast<uint32_t*>(&h0);
        o.y = *reinterpret_cast<uint32_t*>(&h1);
        o.z = *reinterpret_cast<uint32_t*>(&h2);
        o.w = *reinterpret_cast<uint32_t*>(&h3);
        __stcs((uint4*)d + i, o);
    }
}

__device__ __forceinline__ float gelu_tanh(float v) {
    float v3 = v * v * v;
    float t  = tanhf(0.7978845608028654f * (v + 0.044715f * v3));
    return 0.5f * v * (1.f + t);
}

// ---------------------------------------------------------------------------
// Gathered per-expert fp16 GEMM. mma.sync m16n8k16, ldmatrix, 3-stage cp.async,
// one barrier per K-iteration, 2 CTAs/SM.
// MODE 0: hbuf = fp16(gelu(Xgather @ w1 + b1)),  A = g_xh gathered, KD = H
// MODE 1: ybuf = hbuf @ w2 + b2 (scatter rows),  A = g_hbuf compact, KD = F
// ---------------------------------------------------------------------------
template<int KD, int MODE>
__global__ __launch_bounds__(256, 2)
void moe_gemm(const __half* __restrict__ Ah,
              const __half* __restrict__ W,
              const float* __restrict__ bias,
              int ND) {
    extern __shared__ __align__(128) char smem[];
    const uint32_t sb = smem_u32(smem);

    const int e    = blockIdx.z;
    const int cnt  = g_count[e];
    const int row0 = blockIdx.y * BM;
    if (row0 >= cnt) return;
    const int col0 = blockIdx.x * BN;
    const int off  = g_offset[e];

    const int tid  = threadIdx.x;
    const int lane = tid & 31, wid = tid >> 5;
    const int wm = wid & 3, wn = wid >> 2;       // 4x2 warp grid, warp tile 32x64

    // ---- cp.async staging (register-lean: bases + u32 offsets + bitmask) ----
    // A: 128 rows x 128B data. 8 segs/row; thread covers 4 rows (ar0 + 32i).
    const int segA = tid & 7;
    const int ar0  = tid >> 3;
    const char* Abase = (const char*)Ah + segA * 16;
    uint32_t aGOff[4]; uint32_t avMask = 0;
#pragma unroll
    for (int i = 0; i < 4; i++) {
        int r = ar0 + 32 * i;
        bool v = (row0 + r) < cnt;
        uint32_t srow;
        if (MODE == 0) srow = v ? (uint32_t)(g_perm[e * T_TOK + row0 + r] >> 1) : 0u;
        else           srow = (uint32_t)(off + (v ? row0 + r : 0));
        aGOff[i] = srow * (uint32_t)(KD * 2);
        if (v) avMask |= (1u << i);
    }
    const uint32_t aDst0 = (uint32_t)(ar0 * A_STRIDE + segA * 16);
    // B: 64 rows x 256B data. 16 segs/row; thread covers 4 rows (br0 + 16i).
    const int segB = tid & 15;
    const int br0  = tid >> 4;
    const char* Bbase = (const char*)(W + (size_t)e * KD * ND + col0 + segB * 8)
                      + (size_t)br0 * ND * 2;
    const uint32_t bStep16 = (uint32_t)(16 * ND * 2);
    const uint32_t kbStep  = (uint32_t)(BK * ND * 2);
    const uint32_t bDst0   = (uint32_t)(br0 * B_STRIDE + segB * 16);

    auto issue_tile = [&](uint32_t ktA, uint32_t kbOff, int st) {
        uint32_t aB = sb + st * STAGE_BYTES;
        uint32_t bB = aB + A_BYTES;
        uint32_t ad = aB + aDst0;
#pragma unroll
        for (int i = 0; i < 4; i++) {
            CP_ASYNC16(ad, Abase + aGOff[i] + ktA, ((avMask >> i) & 1) ? 16u : 0u);
            ad += 32 * A_STRIDE;
        }
        uint32_t bd = bB + bDst0;
        const char* bs = Bbase + kbOff;
#pragma unroll
        for (int i = 0; i < 4; i++) {
            CP_ASYNC16(bd, bs, 16u);
            bd += 16 * B_STRIDE;
            bs += bStep16;
        }
    };

    // ---- ldmatrix fragment offsets (stage-relative) ----
    int aOff[2];
#pragma unroll
    for (int mf = 0; mf < 2; mf++)
        aOff[mf] = (wm * 32 + mf * 16 + (lane & 15)) * A_STRIDE + (lane >> 4) * 16;
    const int bRow = (lane & 7) + ((lane >> 3) & 1) * 8;
    int bOff[4];
#pragma unroll
    for (int p = 0; p < 4; p++)
        bOff[p] = bRow * B_STRIDE + (wn * 64 + p * 16 + (lane >> 4) * 8) * 2;

    float c[2][8][4];
#pragma unroll
    for (int i = 0; i < 2; i++)
#pragma unroll
        for (int j = 0; j < 8; j++)
#pragma unroll
            for (int q = 0; q < 4; q++) c[i][j][q] = 0.f;

    const int nk = KD / BK;
    uint32_t nxtA = 0, nxtB = 0;
#pragma unroll
    for (int s = 0; s < NSTAGE - 1; s++) {
        issue_tile(nxtA, nxtB, s);
        CP_COMMIT();
        nxtA += BK * 2; nxtB += kbStep;
    }

    for (int kt = 0; kt < nk; kt++) {
        CP_WAITG(NSTAGE - 2);      // groups committed every iter -> tile kt landed
        __syncthreads();           // stage (kt-1)%NSTAGE now reusable
        int nt = kt + NSTAGE - 1;
        if (nt < nk) {
            issue_tile(nxtA, nxtB, nt % NSTAGE);
            nxtA += BK * 2; nxtB += kbStep;
        }
        CP_COMMIT();               // unconditional: keeps group accounting uniform

        uint32_t aB = sb + (kt % NSTAGE) * STAGE_BYTES;
        uint32_t bB = aB + A_BYTES;
#pragma unroll
        for (int ks = 0; ks < 4; ks++) {       // 4 x K=16 = BK
            uint32_t af[2][4], bf[8][2];
#pragma unroll
            for (int mf = 0; mf < 2; mf++)
                LDSM_X4(af[mf][0], af[mf][1], af[mf][2], af[mf][3],
                        aB + aOff[mf] + ks * 32);
#pragma unroll
            for (int p = 0; p < 4; p++)
                LDSM_X4_T(bf[2 * p][0], bf[2 * p][1], bf[2 * p + 1][0], bf[2 * p + 1][1],
                          bB + bOff[p] + ks * 16 * B_STRIDE);
#pragma unroll
            for (int mf = 0; mf < 2; mf++)
#pragma unroll
                for (int nf = 0; nf < 8; nf++)
                    MMA16816(c[mf][nf][0], c[mf][nf][1], c[mf][nf][2], c[mf][nf][3],
                             af[mf][0], af[mf][1], af[mf][2], af[mf][3],
                             bf[nf][0], bf[nf][1]);
        }
    }
    CP_WAITG(0);

    // ---- epilogue: c frag rows (g, g+8), cols (2*tg, 2*tg+1) ----
    const int g  = lane >> 2, tg = lane & 3;
    const float* bz = bias + e * ND + col0;
#pragma unroll
    for (int mf = 0; mf < 2; mf++) {
#pragma unroll
        for (int hh = 0; hh < 2; hh++) {
            int r    = wm * 32 + mf * 16 + g + hh * 8;
            int grow = row0 + r;
            if (grow >= cnt) continue;
            size_t drow;
            if (MODE == 0) drow = (size_t)(off + grow) * F_DIM;
            else           drow = (size_t)g_perm[e * T_TOK + grow] * H_DIM;
#pragma unroll
            for (int nf = 0; nf < 8; nf++) {
                int cn   = wn * 64 + nf * 8 + 2 * tg;
                float v0 = c[mf][nf][hh * 2 + 0] + bz[cn];
                float v1 = c[mf][nf][hh * 2 + 1] + bz[cn + 1];
                if (MODE == 0) {
                    *(__half2*)&g_hbuf[drow + col0 + cn] =
                        __floats2half2_rn(gelu_tanh(v0), gelu_tanh(v1));
                } else {
                    *(float2*)&g_ybuf[drow + col0 + cn] = make_float2(v0, v1);
                }
            }
        }
    }
}

// ---------------------------------------------------------------------------
__global__ __launch_bounds__(256)
void combine_kernel(float* __restrict__ out) {
    int idx = blockIdx.x * blockDim.x + threadIdx.x;   // over T*H/4
    if (idx >= T_TOK * H_DIM / 4) return;
    int t  = idx >> 8;           // H_DIM/4 = 256
    int h4 = (idx & 255) * 4;
    float w0 = g_wslot[2 * t], w1 = g_wslot[2 * t + 1];
    float4 a = *(const float4*)&g_ybuf[(size_t)(2 * t)     * H_DIM + h4];
    float4 b = *(const float4*)&g_ybuf[(size_t)(2 * t + 1) * H_DIM + h4];
    float4 o;
    o.x = w0 * a.x + w1 * b.x;
    o.y = w0 * a.y + w1 * b.y;
    o.z = w0 * a.z + w1 * b.z;
    o.w = w0 * a.w + w1 * b.w;
    ((float4*)out)[idx] = o;
}

// ---------------------------------------------------------------------------
extern "C" void kernel_launch(void* const* d_in, const int* in_sizes, int n_in,
                              void* d_out, int out_size) {
    const float* x  = (const float*)d_in[0];
    const float* w1 = (const float*)d_in[1];
    const float* b1 = (const float*)d_in[2];
    const float* w2 = (const float*)d_in[3];
    const float* b2 = (const float*)d_in[4];
    const float* rw = (const float*)d_in[5];
    const float* rb = (const float*)d_in[6];
    float* out = (float*)d_out;

    cudaFuncSetAttribute(moe_gemm<H_DIM, 0>, cudaFuncAttributeMaxDynamicSharedMemorySize, SM_TOTAL);
    cudaFuncSetAttribute(moe_gemm<F_DIM, 1>, cudaFuncAttributeMaxDynamicSharedMemorySize, SM_TOTAL);

    __half *w1h, *w2h, *xh, *hb;
    cudaGetSymbolAddress((void**)&w1h, g_w1h);
    cudaGetSymbolAddress((void**)&w2h, g_w2h);
    cudaGetSymbolAddress((void**)&xh,  g_xh);
    cudaGetSymbolAddress((void**)&hb,  g_hbuf);

    // weight converts first; the first one also zeroes the expert counters
    {
        int n8 = NEXP * H_DIM * F_DIM / 8;
        f32_to_f16_kernel<<<2048, 256>>>(w1, w1h, n8, 1);
        f32_to_f16_kernel<<<2048, 256>>>(w2, w2h, n8, 0);
    }
    router_kernel<<<T_TOK / 8, 256>>>(x, rw, rb);   // also emits g_xh (fp16)
    scan_kernel<<<1, 1>>>();

    dim3 g1(F_DIM / BN, T_TOK / BM, NEXP);   // 32 x 64 x 8
    moe_gemm<H_DIM, 0><<<g1, 256, SM_TOTAL>>>(xh, w1h, b1, F_DIM);

    dim3 g2(H_DIM / BN, T_TOK / BM, NEXP);   // 8 x 64 x 8
    moe_gemm<F_DIM, 1><<<g2, 256, SM_TOTAL>>>(hb, w2h, b2, H_DIM);

    combine_kernel<<<(T_TOK * H_DIM / 4 + 255) / 256, 256>>>(out);
}